// round 9
// baseline (speedup 1.0000x reference)
#include <cuda_runtime.h>
#include <cuda_bf16.h>
#include <cooperative_groups.h>
#include <cstdint>

namespace cg = cooperative_groups;

#define Bx 16
#define Sx 32
#define Hx 768
#define Ex 200000
#define Tx 200000
#define Rx 500
#define RP 512
#define STx 3
#define WYx 2
#define WTx 6           // WAYS*STEPS, wt = w*3 + t
#define CAP 4096        // max active entities per (step, batch)
#define MCAP 8192       // max matched triples per (step, batch)
#define BMW 6250        // bitmap words per batch
#define ZK  8           // split-K chunks for dense GEMVs (768/96)
#define NT  128         // threads per block

// task counts (retuned for 128-thread blocks)
#define S1B   (WTx*6*2*ZK)  // 576: step-GEMM tasks (wt, hc of 128, half, z)
#define HOPB  (Bx*WYx)      // 32
#define ZSB   1563          // zero+scan tasks: 800000 float4 / (128 thr * 4)
#define FCHK0 196           // find0 chunks per batch: 25000 groups-of-8 / 128
#define FB0   (FCHK0*Bx)    // 3136
#define FCHK2 98            // find1/2 chunks per batch: 12500 groups-of-16 / 128
#define FB2   (FCHK2*Bx)    // 1568
#define CTXB  (Bx*WTx)      // 96
#define S3B   (WTx*4*2*ZK)  // 384: rel-GEMM tasks (wt, rc of 128, half, z)

#define NA (S1B + HOPB + ZSB)
#define NB (CTXB + FB0)
#define NC (S3B + FB2)
#define ND FB2

// ---- persistent device state (zero-init; invariants restored every launch) ----
__device__ float    g_buf[(size_t)WTx * Bx * Ex];
__device__ float    g_ctx[WTx * Bx * Hx];
__device__ float    g_hop[WYx * Bx * STx];
__device__ float    g_p1 [ZK * WTx * Bx * Hx];
__device__ float    g_p3 [ZK * WTx * Bx * RP];
__device__ int      g_subs[(size_t)Bx * Tx];
__device__ int      g_act [4][Bx][CAP];
__device__ int      g_acnt[4][Bx];
__device__ unsigned g_bm  [4][Bx][BMW];
__device__ int      g_match[STx][Bx][MCAP];
__device__ int      g_mcnt[STx][Bx];

// ---------------------------------------------------------------------------
__device__ __forceinline__ void record_match(int t, int b, int ti, int o) {
    int idx = atomicAdd(&g_mcnt[t][b], 1);
    if (idx < MCAP) g_match[t][b][idx] = ti;
    const unsigned bit = 1u << (o & 31);
    const unsigned old = atomicOr(&g_bm[t + 1][b][o >> 5], bit);
    if (!(old & bit)) {
        int ai = atomicAdd(&g_acnt[t + 1][b], 1);
        if (ai < CAP) g_act[t + 1][b][ai] = o;
    }
}

// ---------------------------------------------------------------------------
// One cooperative kernel, 5 phases separated by grid.sync():
//   A: step-GEMM partials || hop || zero-out + heads scan
//   B: ctx || find0 (stream triples MLP=6, extract subs, build list 1)
//   C: rel-GEMM partials || find1 (subs MLP=4)
//   D: find2
//   E: apply matched values + final combine + cleanup (per batch)
// ---------------------------------------------------------------------------
__global__ void __launch_bounds__(NT, 10)
KAll(float* __restrict__ out, const float* __restrict__ heads,
     const float* __restrict__ q_emb, const float* __restrict__ q_word_h,
     const float* __restrict__ mask, const float* __restrict__ step_W,
     const float* __restrict__ step_b, const float* __restrict__ rel_W,
     const float* __restrict__ rel_b, const float* __restrict__ hop_W,
     const float* __restrict__ hop_b, const int* __restrict__ triples) {
    cg::grid_group grid = cg::this_grid();
    __shared__ float s_mem[832];
    const int tid = threadIdx.x;

    // ================= Phase A =============================================
    for (int task = blockIdx.x; task < NA; task += gridDim.x) {
        if (task < S1B) {
            int r = task;
            const int wt = r % WTx; r /= WTx;
            const int hc = r % 6;   r /= 6;
            const int half = r % 2; r /= 2;
            const int z = r;
            const int h0 = z * 96, b0 = half * 8;
            float (*sq)[96] = reinterpret_cast<float (*)[96]>(s_mem);
            for (int i = tid; i < 8 * 96; i += NT)
                sq[i / 96][i % 96] = q_emb[(b0 + i / 96) * Hx + h0 + i % 96];
            __syncthreads();
            const int h2 = hc * NT + tid;
            float acc[8];
#pragma unroll
            for (int j = 0; j < 8; j++) acc[j] = 0.f;
            const float* W = step_W + (size_t)wt * Hx * Hx + (size_t)h0 * Hx + h2;
#pragma unroll 4
            for (int h = 0; h < 96; h++) {
                float wv = W[(size_t)h * Hx];
#pragma unroll
                for (int j = 0; j < 8; j++) acc[j] += sq[j][h] * wv;
            }
#pragma unroll
            for (int j = 0; j < 8; j++)
                g_p1[((size_t)(z * WTx + wt) * Bx + b0 + j) * Hx + h2] = acc[j];
            __syncthreads();
        } else if (task < S1B + HOPB) {
            const int idx = task - S1B;
            const int b = idx % Bx, w = idx / Bx;
            const int s = tid >> 5, lane = tid & 31;
            if (s < STx) {
                float acc = 0.f;
                for (int h = lane; h < Hx; h += 32)
                    acc += q_emb[b * Hx + h] * hop_W[((size_t)w * Hx + h) * STx + s];
                for (int o = 16; o; o >>= 1) acc += __shfl_xor_sync(0xffffffffu, acc, o);
                if (lane == 0) s_mem[s] = acc + hop_b[w * STx + s];
            }
            __syncthreads();
            if (tid == 0) {
                float l0 = s_mem[0], l1 = s_mem[1], l2 = s_mem[2];
                float mm = fmaxf(l0, fmaxf(l1, l2));
                float e0 = expf(l0 - mm), e1 = expf(l1 - mm), e2 = expf(l2 - mm);
                float sum = e0 + e1 + e2;
                g_hop[(w * Bx + b) * STx + 0] = e0 / sum;
                g_hop[(w * Bx + b) * STx + 1] = e1 / sum;
                g_hop[(w * Bx + b) * STx + 2] = e2 / sum;
            }
            __syncthreads();
        } else {
            // zero out + heads scan: 4 independent float4 per thread (MLP=4)
            const size_t base = (size_t)(task - S1B - HOPB) * (NT * 4);
            float4 h4[4];
            size_t i4[4];
            bool ok[4];
#pragma unroll
            for (int k = 0; k < 4; k++) {
                i4[k] = base + k * NT + tid;
                ok[k] = i4[k] < (size_t)Bx * Ex / 4;
                if (ok[k]) h4[k] = reinterpret_cast<const float4*>(heads)[i4[k]];
            }
#pragma unroll
            for (int k = 0; k < 4; k++) {
                if (!ok[k]) continue;
                reinterpret_cast<float4*>(out)[i4[k]] = make_float4(0.f, 0.f, 0.f, 0.f);
                const size_t eb = i4[k] * 4;
                const int b = (int)(eb / Ex);
                const int e0 = (int)(eb % Ex);
                const float v[4] = {h4[k].x, h4[k].y, h4[k].z, h4[k].w};
#pragma unroll
                for (int j = 0; j < 4; j++) {
                    if (v[j] != 0.f) {
                        int e = e0 + j;
                        atomicOr(&g_bm[0][b][e >> 5], 1u << (e & 31));
                        int idx = atomicAdd(&g_acnt[0][b], 1);
                        if (idx < CAP) g_act[0][b][idx] = e;
                    }
                }
            }
        }
    }
    grid.sync();

    // ================= Phase B: ctx || find0 ================================
    for (int task = blockIdx.x; task < NB; task += gridDim.x) {
        if (task < CTXB) {
            float* s_cq = s_mem;
            float* s_l  = s_mem + Hx;
            const int b = task % Bx, wt = task / Bx;
            for (int h = tid; h < Hx; h += NT) {
                float s = step_b[wt * Hx + h];
#pragma unroll
                for (int z = 0; z < ZK; z++) s += g_p1[((size_t)(z * WTx + wt) * Bx + b) * Hx + h];
                s_cq[h] = tanhf(s);
            }
            __syncthreads();
            {   // logits: 4 warps x 8 s each
                const int warp = tid >> 5, lane = tid & 31;
#pragma unroll
                for (int ss = 0; ss < 8; ss++) {
                    const int s = ss * 4 + warp;
                    const float* row = q_word_h + ((size_t)b * Sx + s) * Hx;
                    float acc = 0.f;
#pragma unroll
                    for (int h = lane; h < Hx; h += 32) acc += s_cq[h] * row[h];
                    for (int o = 16; o; o >>= 1) acc += __shfl_xor_sync(0xffffffffu, acc, o);
                    if (lane == 0) s_l[s] = acc;
                }
            }
            __syncthreads();
            if (tid < 32) {
                float v = s_l[tid];
                float mm = v;
                for (int o = 16; o; o >>= 1) mm = fmaxf(mm, __shfl_xor_sync(0xffffffffu, mm, o));
                float e = expf(v - mm);
                float sum = e;
                for (int o = 16; o; o >>= 1) sum += __shfl_xor_sync(0xffffffffu, sum, o);
                float qd = (e / sum) * mask[b * Sx + tid];
                float s2 = qd;
                for (int o = 16; o; o >>= 1) s2 += __shfl_xor_sync(0xffffffffu, s2, o);
                s_l[tid] = qd / (s2 + 1e-6f);
            }
            __syncthreads();
            for (int h = tid; h < Hx; h += NT) {
                float acc = 0.f;
#pragma unroll 8
                for (int s = 0; s < Sx; s++) acc += s_l[s] * q_word_h[((size_t)b * Sx + s) * Hx + h];
                g_ctx[(size_t)(wt * Bx + b) * Hx + h] = acc;
            }
            __syncthreads();
        } else {
            // find0: 8 triples per thread (6 independent int4 loads, MLP=6)
            const int fb = task - CTXB;
            const int b = fb / FCHK0;
            const int g = (fb % FCHK0) * NT + tid;
            if (g >= Tx / 8) continue;
            const size_t i0 = (size_t)g * 8;
            const int4* p = reinterpret_cast<const int4*>(triples + ((size_t)b * Tx + i0) * 3);
            const int4 p0 = p[0], p1 = p[1], p2 = p[2], p3 = p[3], p4 = p[4], p5 = p[5];
            const int sub[8] = {p0.x, p0.w, p1.z, p2.y, p3.x, p3.w, p4.z, p5.y};
            const int obj[8] = {p0.z, p1.y, p2.x, p2.w, p3.z, p4.y, p5.x, p5.w};
            reinterpret_cast<int4*>(g_subs)[((size_t)b * Tx + i0) / 4]     = make_int4(sub[0], sub[1], sub[2], sub[3]);
            reinterpret_cast<int4*>(g_subs)[((size_t)b * Tx + i0) / 4 + 1] = make_int4(sub[4], sub[5], sub[6], sub[7]);
            const int cnt = g_acnt[0][b];
            if (cnt == 0) continue;
            bool m[8] = {false, false, false, false, false, false, false, false};
            if (cnt <= 64) {
                const int* lst = g_act[0][b];
                for (int j = 0; j < cnt; j++) {
                    const int a = lst[j];
#pragma unroll
                    for (int k = 0; k < 8; k++) m[k] |= (sub[k] == a);
                }
            } else {
#pragma unroll
                for (int k = 0; k < 8; k++)
                    m[k] = (g_bm[0][b][sub[k] >> 5] >> (sub[k] & 31)) & 1u;
            }
            bool any = false;
#pragma unroll
            for (int k = 0; k < 8; k++) any |= m[k];
            if (!any) continue;
#pragma unroll
            for (int k = 0; k < 8; k++)
                if (m[k]) record_match(0, b, (int)(i0 + k), obj[k]);
        }
    }
    grid.sync();

    // ================= Phase C: s3 partials || find1 ========================
    for (int task = blockIdx.x; task < NC; task += gridDim.x) {
        if (task < S3B) {
            int r = task;
            const int wt = r % WTx; r /= WTx;
            const int rc = r % 4;   r /= 4;
            const int half = r % 2; r /= 2;
            const int z = r;
            const int w = wt / STx;
            const int h0 = z * 96, b0 = half * 8;
            float (*sc)[96] = reinterpret_cast<float (*)[96]>(s_mem);
            for (int i = tid; i < 8 * 96; i += NT)
                sc[i / 96][i % 96] = g_ctx[(size_t)(wt * Bx + b0 + i / 96) * Hx + h0 + i % 96];
            __syncthreads();
            const int rr = rc * NT + tid;
            if (rr < Rx) {
                float acc[8];
#pragma unroll
                for (int j = 0; j < 8; j++) acc[j] = 0.f;
                const float* W = rel_W + ((size_t)w * Hx + h0) * Rx + rr;
#pragma unroll 4
                for (int h = 0; h < 96; h++) {
                    float wv = W[(size_t)h * Rx];
#pragma unroll
                    for (int j = 0; j < 8; j++) acc[j] += sc[j][h] * wv;
                }
#pragma unroll
                for (int j = 0; j < 8; j++)
                    g_p3[((size_t)(z * WTx + wt) * Bx + b0 + j) * RP + rr] = acc[j];
            }
            __syncthreads();
        } else {
            // find1: 16 subs per thread (4 independent int4 loads, MLP=4)
            const int fb = task - S3B;
            const int b = fb / FCHK2;
            const int cnt = g_acnt[1][b];
            if (cnt == 0) continue;
            const int g = (fb % FCHK2) * NT + tid;
            if (g >= Tx / 16) continue;
            const size_t i0 = (size_t)g * 16;
            const int4* sp = reinterpret_cast<const int4*>(g_subs + (size_t)b * Tx + i0);
            int4 s4[4];
#pragma unroll
            for (int q = 0; q < 4; q++) s4[q] = sp[q];
            const int* sub = reinterpret_cast<const int*>(s4);
            bool m[16];
            if (cnt <= 64) {
                const int* lst = g_act[1][b];
#pragma unroll
                for (int k = 0; k < 16; k++) m[k] = false;
                for (int j = 0; j < cnt; j++) {
                    const int a = lst[j];
#pragma unroll
                    for (int k = 0; k < 16; k++) m[k] |= (sub[k] == a);
                }
            } else {
#pragma unroll
                for (int k = 0; k < 16; k++)
                    m[k] = (g_bm[1][b][sub[k] >> 5] >> (sub[k] & 31)) & 1u;
            }
            bool any = false;
#pragma unroll
            for (int k = 0; k < 16; k++) any |= m[k];
            if (!any) continue;
#pragma unroll
            for (int k = 0; k < 16; k++) {
                if (!m[k]) continue;
                const int ti = (int)(i0 + k);
                record_match(1, b, ti, triples[((size_t)b * Tx + ti) * 3 + 2]);
            }
        }
    }
    grid.sync();

    // ================= Phase D: find2 =======================================
    for (int task = blockIdx.x; task < ND; task += gridDim.x) {
        const int b = task / FCHK2;
        const int cnt = g_acnt[2][b];
        if (cnt == 0) continue;
        const int g = (task % FCHK2) * NT + tid;
        if (g >= Tx / 16) continue;
        const size_t i0 = (size_t)g * 16;
        const int4* sp = reinterpret_cast<const int4*>(g_subs + (size_t)b * Tx + i0);
        int4 s4[4];
#pragma unroll
        for (int q = 0; q < 4; q++) s4[q] = sp[q];
        const int* sub = reinterpret_cast<const int*>(s4);
        bool m[16];
        if (cnt <= 64) {
            const int* lst = g_act[2][b];
#pragma unroll
            for (int k = 0; k < 16; k++) m[k] = false;
            for (int j = 0; j < cnt; j++) {
                const int a = lst[j];
#pragma unroll
                for (int k = 0; k < 16; k++) m[k] |= (sub[k] == a);
            }
        } else {
#pragma unroll
            for (int k = 0; k < 16; k++)
                m[k] = (g_bm[2][b][sub[k] >> 5] >> (sub[k] & 31)) & 1u;
        }
        bool any = false;
#pragma unroll
        for (int k = 0; k < 16; k++) any |= m[k];
        if (!any) continue;
#pragma unroll
        for (int k = 0; k < 16; k++) {
            if (!m[k]) continue;
            const int ti = (int)(i0 + k);
            record_match(2, b, ti, triples[((size_t)b * Tx + ti) * 3 + 2]);
        }
    }
    grid.sync();

    // ================= Phase E: apply + final + cleanup =====================
    for (int b = blockIdx.x; b < Bx; b += gridDim.x) {
        for (int t = 0; t < STx; t++) {
            const int mc = min(g_mcnt[t][b], MCAP);
            for (int i = tid; i < mc; i += NT) {
                const int ti = g_match[t][b][i];
                const int* tr = triples + ((size_t)b * Tx + ti) * 3;
                const int sub = tr[0], rel = tr[1], obj = tr[2];
                float v0, v1;
                if (t == 0) {
                    v0 = fminf(heads[(size_t)b * Ex + sub], 1.f);
                    v1 = v0;
                } else {
                    v0 = fminf(g_buf[((size_t)(0 * STx + t - 1) * Bx + b) * Ex + sub], 1.f);
                    v1 = fminf(g_buf[((size_t)(1 * STx + t - 1) * Bx + b) * Ex + sub], 1.f);
                }
                float r0 = rel_b[0 * Rx + rel], r1 = rel_b[1 * Rx + rel];
#pragma unroll
                for (int z = 0; z < ZK; z++) {
                    r0 += g_p3[((size_t)(z * WTx + 0 * STx + t) * Bx + b) * RP + rel];
                    r1 += g_p3[((size_t)(z * WTx + 1 * STx + t) * Bx + b) * RP + rel];
                }
                r0 = 1.f / (1.f + expf(-r0));
                r1 = 1.f / (1.f + expf(-r1));
                atomicAdd(&g_buf[((size_t)(0 * STx + t) * Bx + b) * Ex + obj], v0 * r0);
                atomicAdd(&g_buf[((size_t)(1 * STx + t) * Bx + b) * Ex + obj], v1 * r1);
            }
            __syncthreads();
        }
        for (int tt = 0; tt < STx; tt++) {
            const int cnt = min(g_acnt[tt + 1][b], CAP);
            for (int i = tid; i < cnt; i += NT) {
                const int e = g_act[tt + 1][b][i];
                float a0 = 0.f, a1 = 0.f;
#pragma unroll
                for (int t = 0; t < STx; t++) {
                    a0 += g_hop[(0 * Bx + b) * STx + t] *
                          fminf(g_buf[((size_t)(0 * STx + t) * Bx + b) * Ex + e], 1.f);
                    a1 += g_hop[(1 * Bx + b) * STx + t] *
                          fminf(g_buf[((size_t)(1 * STx + t) * Bx + b) * Ex + e], 1.f);
                }
                out[(size_t)b * Ex + e] = a0 * a1;
            }
        }
        __syncthreads();
        for (int tt = 0; tt < STx; tt++) {
            const int cnt = min(g_acnt[tt + 1][b], CAP);
            for (int i = tid; i < cnt; i += NT) {
                const int e = g_act[tt + 1][b][i];
                g_buf[((size_t)(0 * STx + tt) * Bx + b) * Ex + e] = 0.f;
                g_buf[((size_t)(1 * STx + tt) * Bx + b) * Ex + e] = 0.f;
                g_bm[tt + 1][b][e >> 5] = 0u;
            }
        }
        {
            const int cnt0 = min(g_acnt[0][b], CAP);
            for (int i = tid; i < cnt0; i += NT)
                g_bm[0][b][g_act[0][b][i] >> 5] = 0u;
        }
        __syncthreads();
        if (tid == 0) {
#pragma unroll
            for (int t = 0; t < 4; t++) g_acnt[t][b] = 0;
#pragma unroll
            for (int t = 0; t < STx; t++) g_mcnt[t][b] = 0;
        }
        __syncthreads();
    }
}

// ---------------------------------------------------------------------------
extern "C" void kernel_launch(void* const* d_in, const int* in_sizes, int n_in,
                              void* d_out, int out_size) {
    const float* heads  = (const float*)d_in[0];
    const float* q_emb  = (const float*)d_in[1];
    const float* qwh    = (const float*)d_in[2];
    const float* mask   = (const float*)d_in[3];
    const float* step_W = (const float*)d_in[4];
    const float* step_b = (const float*)d_in[5];
    const float* rel_W  = (const float*)d_in[6];
    const float* rel_b  = (const float*)d_in[7];
    const float* hop_W  = (const float*)d_in[8];
    const float* hop_b  = (const float*)d_in[9];
    const int*   triples = (const int*)d_in[10];
    float* out = (float*)d_out;

    static int g_grid = 0;
    if (g_grid == 0) {   // host-only; computed on the uncaptured first call
        int dev = 0; cudaGetDevice(&dev);
        int sms = 0; cudaDeviceGetAttribute(&sms, cudaDevAttrMultiProcessorCount, dev);
        int bpm = 0;
        cudaOccupancyMaxActiveBlocksPerMultiprocessor(&bpm, KAll, NT, 0);
        if (bpm < 1) bpm = 1;
        g_grid = bpm * sms;
    }

    void* args[] = {&out, (void*)&heads, (void*)&q_emb, (void*)&qwh, (void*)&mask,
                    (void*)&step_W, (void*)&step_b, (void*)&rel_W, (void*)&rel_b,
                    (void*)&hop_W, (void*)&hop_b, (void*)&triples};
    cudaLaunchCooperativeKernel((const void*)KAll, dim3(g_grid), dim3(NT), args, 0, 0);
}

// round 10
// speedup vs baseline: 1.4735x; 1.4735x over previous
#include <cuda_runtime.h>
#include <cuda_bf16.h>
#include <cooperative_groups.h>
#include <cstdint>

namespace cg = cooperative_groups;

#define Bx 16
#define Sx 32
#define Hx 768
#define Ex 200000
#define Tx 200000
#define Rx 500
#define RP 512
#define STx 3
#define WYx 2
#define WTx 6           // WAYS*STEPS, wt = w*3 + t
#define CAP 4096
#define MCAP 8192
#define BMW 6250
#define ZK  8           // split-K chunks for dense GEMVs (768/96)
#define NT  256

// task counts (256-thread blocks, as in the 90.8us best)
#define S1B   (WTx*3*2*ZK)  // 288
#define HOPB  (Bx*WYx)      // 32
#define ZSB   782           // 800000 float4 / (256*4)
#define FCHK0 98            // 25000 groups-of-8 / 256
#define FB0   (FCHK0*Bx)    // 1568
#define FCHK2 49            // 12500 groups-of-16 / 256
#define FB2   (FCHK2*Bx)    // 784
#define CTXB  (Bx*WTx)      // 96
#define S3B   (WTx*2*2*ZK)  // 192

#define NA (S1B + HOPB + ZSB)
#define NB (CTXB + FB0)
#define NC (S3B + FB2)
#define ND FB2

// ---- persistent device state ----
__device__ float    g_buf[(size_t)WTx * Bx * Ex];
__device__ float    g_ctx[WTx * Bx * Hx];
__device__ float    g_hop[WYx * Bx * STx];
__device__ float    g_p1 [ZK * WTx * Bx * Hx];
__device__ float    g_p3 [ZK * WTx * Bx * RP];
__device__ int      g_subs[(size_t)Bx * Tx];
__device__ int      g_act [4][Bx][CAP];
__device__ int      g_acnt[4][Bx];
__device__ unsigned g_bm  [4][Bx][BMW];
__device__ int      g_match[STx][Bx][MCAP];
__device__ int      g_mcnt[STx][Bx];

// ---------------------------------------------------------------------------
__device__ __forceinline__ void record_match(int t, int b, int ti, int o) {
    int idx = atomicAdd(&g_mcnt[t][b], 1);
    if (idx < MCAP) g_match[t][b][idx] = ti;
    const unsigned bit = 1u << (o & 31);
    const unsigned old = atomicOr(&g_bm[t + 1][b][o >> 5], bit);
    if (!(old & bit)) {
        int ai = atomicAdd(&g_acnt[t + 1][b], 1);
        if (ai < CAP) g_act[t + 1][b][ai] = o;
    }
}

// ---------------------------------------------------------------------------
__global__ void __launch_bounds__(NT, 4)
KAll(float* __restrict__ out, const float* __restrict__ heads,
     const float* __restrict__ q_emb, const float* __restrict__ q_word_h,
     const float* __restrict__ mask, const float* __restrict__ step_W,
     const float* __restrict__ step_b, const float* __restrict__ rel_W,
     const float* __restrict__ rel_b, const float* __restrict__ hop_W,
     const float* __restrict__ hop_b, const int* __restrict__ triples) {
    cg::grid_group grid = cg::this_grid();
    __shared__ float s_mem[832];
    const int tid = threadIdx.x;

    // ================= Phase A: s1 || hop || zero+scan ======================
    for (int task = blockIdx.x; task < NA; task += gridDim.x) {
        if (task < S1B) {
            int r = task;
            const int wt = r % WTx; r /= WTx;
            const int hc = r % 3;   r /= 3;
            const int half = r % 2; r /= 2;
            const int z = r;
            const int h0 = z * 96, b0 = half * 8;
            float (*sq)[96] = reinterpret_cast<float (*)[96]>(s_mem);
            for (int i = tid; i < 8 * 96; i += NT)
                sq[i / 96][i % 96] = q_emb[(b0 + i / 96) * Hx + h0 + i % 96];
            __syncthreads();
            const int h2 = hc * NT + tid;
            float acc[8];
#pragma unroll
            for (int j = 0; j < 8; j++) acc[j] = 0.f;
            const float* W = step_W + (size_t)wt * Hx * Hx + (size_t)h0 * Hx + h2;
#pragma unroll
            for (int hh = 0; hh < 96; hh += 16) {
                float wv[16];                       // 16 independent loads in flight
#pragma unroll
                for (int u = 0; u < 16; u++) wv[u] = W[(size_t)(hh + u) * Hx];
#pragma unroll
                for (int u = 0; u < 16; u++)
#pragma unroll
                    for (int j = 0; j < 8; j++) acc[j] += sq[j][hh + u] * wv[u];
            }
#pragma unroll
            for (int j = 0; j < 8; j++)
                g_p1[((size_t)(z * WTx + wt) * Bx + b0 + j) * Hx + h2] = acc[j];
            __syncthreads();
        } else if (task < S1B + HOPB) {
            const int idx = task - S1B;
            const int b = idx % Bx, w = idx / Bx;
            const int s = tid >> 5, lane = tid & 31;
            if (s < STx) {
                float acc = 0.f;
#pragma unroll
                for (int hh = 0; hh < 24; hh += 8) {
                    float qv[8], wv[8];             // 16 loads in flight
#pragma unroll
                    for (int u = 0; u < 8; u++) {
                        const int h = lane + 32 * (hh + u);
                        qv[u] = q_emb[b * Hx + h];
                        wv[u] = hop_W[((size_t)w * Hx + h) * STx + s];
                    }
#pragma unroll
                    for (int u = 0; u < 8; u++) acc += qv[u] * wv[u];
                }
                for (int o = 16; o; o >>= 1) acc += __shfl_xor_sync(0xffffffffu, acc, o);
                if (lane == 0) s_mem[s] = acc + hop_b[w * STx + s];
            }
            __syncthreads();
            if (tid == 0) {
                float l0 = s_mem[0], l1 = s_mem[1], l2 = s_mem[2];
                float mm = fmaxf(l0, fmaxf(l1, l2));
                float e0 = expf(l0 - mm), e1 = expf(l1 - mm), e2 = expf(l2 - mm);
                float sum = e0 + e1 + e2;
                g_hop[(w * Bx + b) * STx + 0] = e0 / sum;
                g_hop[(w * Bx + b) * STx + 1] = e1 / sum;
                g_hop[(w * Bx + b) * STx + 2] = e2 / sum;
            }
            __syncthreads();
        } else {
            const size_t base = (size_t)(task - S1B - HOPB) * (NT * 4);
            float4 h4[4];
            size_t i4[4];
            bool ok[4];
#pragma unroll
            for (int k = 0; k < 4; k++) {
                i4[k] = base + k * NT + tid;
                ok[k] = i4[k] < (size_t)Bx * Ex / 4;
                if (ok[k]) h4[k] = reinterpret_cast<const float4*>(heads)[i4[k]];
            }
#pragma unroll
            for (int k = 0; k < 4; k++) {
                if (!ok[k]) continue;
                reinterpret_cast<float4*>(out)[i4[k]] = make_float4(0.f, 0.f, 0.f, 0.f);
                const size_t eb = i4[k] * 4;
                const int b = (int)(eb / Ex);
                const int e0 = (int)(eb % Ex);
                const float v[4] = {h4[k].x, h4[k].y, h4[k].z, h4[k].w};
#pragma unroll
                for (int j = 0; j < 4; j++) {
                    if (v[j] != 0.f) {
                        int e = e0 + j;
                        atomicOr(&g_bm[0][b][e >> 5], 1u << (e & 31));
                        int idx = atomicAdd(&g_acnt[0][b], 1);
                        if (idx < CAP) g_act[0][b][idx] = e;
                    }
                }
            }
        }
    }
    grid.sync();

    // ================= Phase B: ctx || find0 ================================
    for (int task = blockIdx.x; task < NB; task += gridDim.x) {
        if (task < CTXB) {
            float* s_cq = s_mem;
            float* s_l  = s_mem + Hx;
            const int b = task % Bx, wt = task / Bx;
            for (int h = tid; h < Hx; h += NT) {
                float pv[ZK];                       // 8 independent loads
#pragma unroll
                for (int z = 0; z < ZK; z++) pv[z] = g_p1[((size_t)(z * WTx + wt) * Bx + b) * Hx + h];
                float s = step_b[wt * Hx + h];
#pragma unroll
                for (int z = 0; z < ZK; z++) s += pv[z];
                s_cq[h] = tanhf(s);
            }
            __syncthreads();
            {   // logits: 8 warps, 4 dots each, accumulated simultaneously
                const int warp = tid >> 5, lane = tid & 31;
                float acc[4] = {0.f, 0.f, 0.f, 0.f};
                const float* base = q_word_h + ((size_t)b * Sx + warp * 4) * Hx + lane;
#pragma unroll
                for (int hh = 0; hh < 24; hh += 4) {
                    float cq[4], rv[16];            // 16 loads in flight
#pragma unroll
                    for (int u = 0; u < 4; u++) cq[u] = s_cq[lane + 32 * (hh + u)];
#pragma unroll
                    for (int ss = 0; ss < 4; ss++)
#pragma unroll
                        for (int u = 0; u < 4; u++)
                            rv[ss * 4 + u] = base[(size_t)ss * Hx + 32 * (hh + u)];
#pragma unroll
                    for (int ss = 0; ss < 4; ss++)
#pragma unroll
                        for (int u = 0; u < 4; u++) acc[ss] += cq[u] * rv[ss * 4 + u];
                }
#pragma unroll
                for (int ss = 0; ss < 4; ss++) {
                    float a = acc[ss];
                    for (int o = 16; o; o >>= 1) a += __shfl_xor_sync(0xffffffffu, a, o);
                    if (lane == 0) s_l[warp * 4 + ss] = a;
                }
            }
            __syncthreads();
            if (tid < 32) {
                float v = s_l[tid];
                float mm = v;
                for (int o = 16; o; o >>= 1) mm = fmaxf(mm, __shfl_xor_sync(0xffffffffu, mm, o));
                float e = expf(v - mm);
                float sum = e;
                for (int o = 16; o; o >>= 1) sum += __shfl_xor_sync(0xffffffffu, sum, o);
                float qd = (e / sum) * mask[b * Sx + tid];
                float s2 = qd;
                for (int o = 16; o; o >>= 1) s2 += __shfl_xor_sync(0xffffffffu, s2, o);
                s_l[tid] = qd / (s2 + 1e-6f);
            }
            __syncthreads();
            for (int h = tid; h < Hx; h += NT) {
                float acc = 0.f;
#pragma unroll
                for (int s = 0; s < Sx; s += 8) {
                    float rv[8];                    // 8 loads in flight
#pragma unroll
                    for (int u = 0; u < 8; u++)
                        rv[u] = q_word_h[((size_t)b * Sx + s + u) * Hx + h];
#pragma unroll
                    for (int u = 0; u < 8; u++) acc += s_l[s + u] * rv[u];
                }
                g_ctx[(size_t)(wt * Bx + b) * Hx + h] = acc;
            }
            __syncthreads();
        } else {
            // find0: 8 triples per thread (6 independent int4 loads)
            const int fb = task - CTXB;
            const int b = fb / FCHK0;
            const int g = (fb % FCHK0) * NT + tid;
            if (g >= Tx / 8) continue;
            const size_t i0 = (size_t)g * 8;
            const int4* p = reinterpret_cast<const int4*>(triples + ((size_t)b * Tx + i0) * 3);
            const int4 p0 = p[0], p1 = p[1], p2 = p[2], p3 = p[3], p4 = p[4], p5 = p[5];
            const int sub[8] = {p0.x, p0.w, p1.z, p2.y, p3.x, p3.w, p4.z, p5.y};
            const int obj[8] = {p0.z, p1.y, p2.x, p2.w, p3.z, p4.y, p5.x, p5.w};
            reinterpret_cast<int4*>(g_subs)[((size_t)b * Tx + i0) / 4]     = make_int4(sub[0], sub[1], sub[2], sub[3]);
            reinterpret_cast<int4*>(g_subs)[((size_t)b * Tx + i0) / 4 + 1] = make_int4(sub[4], sub[5], sub[6], sub[7]);
            const int cnt = g_acnt[0][b];
            if (cnt == 0) continue;
            bool m[8] = {false, false, false, false, false, false, false, false};
            if (cnt <= 64) {
                const int* lst = g_act[0][b];
                for (int j = 0; j < cnt; j++) {
                    const int a = lst[j];
#pragma unroll
                    for (int k = 0; k < 8; k++) m[k] |= (sub[k] == a);
                }
            } else {
#pragma unroll
                for (int k = 0; k < 8; k++)
                    m[k] = (g_bm[0][b][sub[k] >> 5] >> (sub[k] & 31)) & 1u;
            }
            bool any = false;
#pragma unroll
            for (int k = 0; k < 8; k++) any |= m[k];
            if (!any) continue;
#pragma unroll
            for (int k = 0; k < 8; k++)
                if (m[k]) record_match(0, b, (int)(i0 + k), obj[k]);
        }
    }
    grid.sync();

    // ================= Phase C: s3 || find1 =================================
    for (int task = blockIdx.x; task < NC; task += gridDim.x) {
        if (task < S3B) {
            int r = task;
            const int wt = r % WTx; r /= WTx;
            const int rc = r % 2;   r /= 2;
            const int half = r % 2; r /= 2;
            const int z = r;
            const int w = wt / STx;
            const int h0 = z * 96, b0 = half * 8;
            float (*sc)[96] = reinterpret_cast<float (*)[96]>(s_mem);
            for (int i = tid; i < 8 * 96; i += NT)
                sc[i / 96][i % 96] = g_ctx[(size_t)(wt * Bx + b0 + i / 96) * Hx + h0 + i % 96];
            __syncthreads();
            const int rr = rc * NT + tid;
            if (rr < Rx) {
                float acc[8];
#pragma unroll
                for (int j = 0; j < 8; j++) acc[j] = 0.f;
                const float* W = rel_W + ((size_t)w * Hx + h0) * Rx + rr;
#pragma unroll
                for (int hh = 0; hh < 96; hh += 16) {
                    float wv[16];                   // 16 loads in flight
#pragma unroll
                    for (int u = 0; u < 16; u++) wv[u] = W[(size_t)(hh + u) * Rx];
#pragma unroll
                    for (int u = 0; u < 16; u++)
#pragma unroll
                        for (int j = 0; j < 8; j++) acc[j] += sc[j][hh + u] * wv[u];
                }
#pragma unroll
                for (int j = 0; j < 8; j++)
                    g_p3[((size_t)(z * WTx + wt) * Bx + b0 + j) * RP + rr] = acc[j];
            }
            __syncthreads();
        } else {
            // find1: 16 subs per thread (4 independent int4 loads)
            const int fb = task - S3B;
            const int b = fb / FCHK2;
            const int cnt = g_acnt[1][b];
            if (cnt == 0) continue;
            const int g = (fb % FCHK2) * NT + tid;
            if (g >= Tx / 16) continue;
            const size_t i0 = (size_t)g * 16;
            const int4* sp = reinterpret_cast<const int4*>(g_subs + (size_t)b * Tx + i0);
            int4 s4[4];
#pragma unroll
            for (int q = 0; q < 4; q++) s4[q] = sp[q];
            const int* sub = reinterpret_cast<const int*>(s4);
            bool m[16];
            if (cnt <= 64) {
                const int* lst = g_act[1][b];
#pragma unroll
                for (int k = 0; k < 16; k++) m[k] = false;
                for (int j = 0; j < cnt; j++) {
                    const int a = lst[j];
#pragma unroll
                    for (int k = 0; k < 16; k++) m[k] |= (sub[k] == a);
                }
            } else {
#pragma unroll
                for (int k = 0; k < 16; k++)
                    m[k] = (g_bm[1][b][sub[k] >> 5] >> (sub[k] & 31)) & 1u;
            }
            bool any = false;
#pragma unroll
            for (int k = 0; k < 16; k++) any |= m[k];
            if (!any) continue;
#pragma unroll
            for (int k = 0; k < 16; k++) {
                if (!m[k]) continue;
                const int ti = (int)(i0 + k);
                record_match(1, b, ti, triples[((size_t)b * Tx + ti) * 3 + 2]);
            }
        }
    }
    grid.sync();

    // ================= Phase D: find2 =======================================
    for (int task = blockIdx.x; task < ND; task += gridDim.x) {
        const int b = task / FCHK2;
        const int cnt = g_acnt[2][b];
        if (cnt == 0) continue;
        const int g = (task % FCHK2) * NT + tid;
        if (g >= Tx / 16) continue;
        const size_t i0 = (size_t)g * 16;
        const int4* sp = reinterpret_cast<const int4*>(g_subs + (size_t)b * Tx + i0);
        int4 s4[4];
#pragma unroll
        for (int q = 0; q < 4; q++) s4[q] = sp[q];
        const int* sub = reinterpret_cast<const int*>(s4);
        bool m[16];
        if (cnt <= 64) {
            const int* lst = g_act[2][b];
#pragma unroll
            for (int k = 0; k < 16; k++) m[k] = false;
            for (int j = 0; j < cnt; j++) {
                const int a = lst[j];
#pragma unroll
                for (int k = 0; k < 16; k++) m[k] |= (sub[k] == a);
            }
        } else {
#pragma unroll
            for (int k = 0; k < 16; k++)
                m[k] = (g_bm[2][b][sub[k] >> 5] >> (sub[k] & 31)) & 1u;
        }
        bool any = false;
#pragma unroll
        for (int k = 0; k < 16; k++) any |= m[k];
        if (!any) continue;
#pragma unroll
        for (int k = 0; k < 16; k++) {
            if (!m[k]) continue;
            const int ti = (int)(i0 + k);
            record_match(2, b, ti, triples[((size_t)b * Tx + ti) * 3 + 2]);
        }
    }
    grid.sync();

    // ================= Phase E: apply + final + cleanup =====================
    for (int b = blockIdx.x; b < Bx; b += gridDim.x) {
        for (int t = 0; t < STx; t++) {
            const int mc = min(g_mcnt[t][b], MCAP);
            for (int i = tid; i < mc; i += NT) {
                const int ti = g_match[t][b][i];
                const int* tr = triples + ((size_t)b * Tx + ti) * 3;
                const int sub = tr[0], rel = tr[1], obj = tr[2];
                float v0, v1;
                if (t == 0) {
                    v0 = fminf(heads[(size_t)b * Ex + sub], 1.f);
                    v1 = v0;
                } else {
                    v0 = fminf(g_buf[((size_t)(0 * STx + t - 1) * Bx + b) * Ex + sub], 1.f);
                    v1 = fminf(g_buf[((size_t)(1 * STx + t - 1) * Bx + b) * Ex + sub], 1.f);
                }
                float r0 = rel_b[0 * Rx + rel], r1 = rel_b[1 * Rx + rel];
#pragma unroll
                for (int z = 0; z < ZK; z++) {
                    r0 += g_p3[((size_t)(z * WTx + 0 * STx + t) * Bx + b) * RP + rel];
                    r1 += g_p3[((size_t)(z * WTx + 1 * STx + t) * Bx + b) * RP + rel];
                }
                r0 = 1.f / (1.f + expf(-r0));
                r1 = 1.f / (1.f + expf(-r1));
                atomicAdd(&g_buf[((size_t)(0 * STx + t) * Bx + b) * Ex + obj], v0 * r0);
                atomicAdd(&g_buf[((size_t)(1 * STx + t) * Bx + b) * Ex + obj], v1 * r1);
            }
            __syncthreads();
        }
        for (int tt = 0; tt < STx; tt++) {
            const int cnt = min(g_acnt[tt + 1][b], CAP);
            for (int i = tid; i < cnt; i += NT) {
                const int e = g_act[tt + 1][b][i];
                float a0 = 0.f, a1 = 0.f;
#pragma unroll
                for (int t = 0; t < STx; t++) {
                    a0 += g_hop[(0 * Bx + b) * STx + t] *
                          fminf(g_buf[((size_t)(0 * STx + t) * Bx + b) * Ex + e], 1.f);
                    a1 += g_hop[(1 * Bx + b) * STx + t] *
                          fminf(g_buf[((size_t)(1 * STx + t) * Bx + b) * Ex + e], 1.f);
                }
                out[(size_t)b * Ex + e] = a0 * a1;
            }
        }
        __syncthreads();
        for (int tt = 0; tt < STx; tt++) {
            const int cnt = min(g_acnt[tt + 1][b], CAP);
            for (int i = tid; i < cnt; i += NT) {
                const int e = g_act[tt + 1][b][i];
                g_buf[((size_t)(0 * STx + tt) * Bx + b) * Ex + e] = 0.f;
                g_buf[((size_t)(1 * STx + tt) * Bx + b) * Ex + e] = 0.f;
                g_bm[tt + 1][b][e >> 5] = 0u;
            }
        }
        {
            const int cnt0 = min(g_acnt[0][b], CAP);
            for (int i = tid; i < cnt0; i += NT)
                g_bm[0][b][g_act[0][b][i] >> 5] = 0u;
        }
        __syncthreads();
        if (tid == 0) {
#pragma unroll
            for (int t = 0; t < 4; t++) g_acnt[t][b] = 0;
#pragma unroll
            for (int t = 0; t < STx; t++) g_mcnt[t][b] = 0;
        }
        __syncthreads();
    }
}

// ---------------------------------------------------------------------------
extern "C" void kernel_launch(void* const* d_in, const int* in_sizes, int n_in,
                              void* d_out, int out_size) {
    const float* heads  = (const float*)d_in[0];
    const float* q_emb  = (const float*)d_in[1];
    const float* qwh    = (const float*)d_in[2];
    const float* mask   = (const float*)d_in[3];
    const float* step_W = (const float*)d_in[4];
    const float* step_b = (const float*)d_in[5];
    const float* rel_W  = (const float*)d_in[6];
    const float* rel_b  = (const float*)d_in[7];
    const float* hop_W  = (const float*)d_in[8];
    const float* hop_b  = (const float*)d_in[9];
    const int*   triples = (const int*)d_in[10];
    float* out = (float*)d_out;

    static int g_grid = 0;
    if (g_grid == 0) {   // host-only; computed on the uncaptured first call
        int dev = 0; cudaGetDevice(&dev);
        int sms = 0; cudaDeviceGetAttribute(&sms, cudaDevAttrMultiProcessorCount, dev);
        int bpm = 0;
        cudaOccupancyMaxActiveBlocksPerMultiprocessor(&bpm, KAll, NT, 0);
        if (bpm < 1) bpm = 1;
        g_grid = bpm * sms;
    }

    void* args[] = {&out, (void*)&heads, (void*)&q_emb, (void*)&qwh, (void*)&mask,
                    (void*)&step_W, (void*)&step_b, (void*)&rel_W, (void*)&rel_b,
                    (void*)&hop_W, (void*)&hop_b, (void*)&triples};
    cudaLaunchCooperativeKernel((const void*)KAll, dim3(g_grid), dim3(NT), args, 0, 0);
}